// round 15
// baseline (speedup 1.0000x reference)
#include <cuda_runtime.h>
#include <stdint.h>

#define BATCH   32768
#define NTREE   256
#define NNODE   2047
#define NFEAT   256
#define NCLS    8
#define DEPTH   10
#define SCHUNK  128
#define THREADS 512           // 128 samples x 4 tree-lanes (2 chains each)
#define GTREES  8
#define NCHUNK  (BATCH / SCHUNK)          // 256
#define NGROUPS (NTREE / GTREES)          // 32
#define NITEMS  (NCHUNK * NGROUPS)        // 8192, chunk-major
#define NSLOT   1024          // 8KB slab per tree (1023 internal nodes used)
#define QBYTES  (2 * NSLOT * 8)           // 16KB: one warp-group's 2 tree slabs

// smem map: [0,128K) x-tile | [128K,192K) node buffer | [192K,+9K) idx x2 | mbar
#define SM_X      0
#define SM_NODES  131072
#define SM_IDX    196608
#define IDX_PITCH 9
#define IDX_BYTES (SCHUNK * IDX_PITCH * 4)   // 4608
#define SM_MBAR   (196608 + 2 * IDX_BYTES)
#define SM_TOTAL  (SM_MBAR + 16)

__device__ uint2 g_nodes2[NTREE * NSLOT];   // internal nodes: {thr bits, feat*512}
__device__ float g_xT[NFEAT * BATCH];       // x transposed [feature][sample]

// ---------------- merged prep: transpose x + pack nodes ----------------
__global__ void prep_k(const float* __restrict__ x,
                       const int* __restrict__ features,
                       const float* __restrict__ thresholds) {
    int b = blockIdx.x;
    const int TBLK = (NFEAT / 32) * (BATCH / 32);
    if (b < TBLK) {
        __shared__ float tile[32][33];
        int f0 = (b & 7) * 32, s0 = (b >> 3) * 32;
        int lx = threadIdx.x & 31, ly = threadIdx.x >> 5;   // 256 threads
        #pragma unroll
        for (int k = ly; k < 32; k += 8)
            tile[k][lx] = x[(size_t)(s0 + k) * NFEAT + f0 + lx];
        __syncthreads();
        #pragma unroll
        for (int k = ly; k < 32; k += 8)
            g_xT[(size_t)(f0 + k) * BATCH + s0 + lx] = tile[lx][k];
    } else {
        int i = (b - TBLK) * 256 + threadIdx.x;
        if (i < NTREE * 1023) {
            int t = i / 1023;
            int n = i - t * 1023;
            int src = t * NNODE + n;
            uint2 v;
            v.x = __float_as_uint(thresholds[src]);
            v.y = (unsigned)features[src] * (SCHUNK * 4);
            g_nodes2[t * NSLOT + n] = v;
        }
    }
}

// ---------------- helpers ----------------
__device__ __forceinline__ void stage_x(char* sm, int s0, int tid) {
    float4* xs4 = (float4*)(sm + SM_X);
    #pragma unroll
    for (int j = 0; j < 16; j++) {
        int i4 = tid + THREADS * j;                 // 8192 float4
        int f = i4 >> 5, o = i4 & 31;
        xs4[i4] = *(const float4*)(g_xT + (size_t)f * BATCH + s0 + o * 4);
    }
}

// fetch one 16KB quarter (2 tree slabs) of group g for warp-group tl
__device__ __forceinline__ void fetch_quarter(unsigned smbase, int g, int tl, unsigned mbar) {
    asm volatile("mbarrier.arrive.expect_tx.shared.b64 _, [%0], %1;"
                 :: "r"(mbar), "r"((unsigned)QBYTES) : "memory");
    const char* src = (const char*)(g_nodes2 + ((size_t)g * GTREES + 2 * tl) * NSLOT);
    unsigned dst = smbase + SM_NODES + tl * QBYTES;
    asm volatile("cp.async.bulk.shared::cta.global.mbarrier::complete_tx::bytes "
                 "[%0], [%1], %2, [%3];"
                 :: "r"(dst), "l"(src), "r"((unsigned)QBYTES), "r"(mbar) : "memory");
}

__device__ __forceinline__ void mbar_wait(unsigned mbar, unsigned parity) {
    unsigned done;
    asm volatile("{\n\t.reg .pred p;\n\t"
                 "mbarrier.try_wait.parity.acquire.cta.shared::cta.b64 p, [%1], %2;\n\t"
                 "selp.b32 %0, 1, 0, p;\n\t}"
                 : "=r"(done) : "r"(mbar), "r"(parity) : "memory");
    if (!done) {
        asm volatile("{\n\t.reg .pred P1;\n\t"
                     "W%=:\n\t"
                     "mbarrier.try_wait.parity.acquire.cta.shared::cta.b64 P1, [%0], %1, 0x989680;\n\t"
                     "@P1 bra.uni D%=;\n\t"
                     "bra.uni W%=;\n\t"
                     "D%=:\n\t}"
                     :: "r"(mbar), "r"(parity) : "memory");
    }
}

// ---------------- main traversal (persistent, quarter-pipelined DMA) ----------------
__global__ __launch_bounds__(THREADS, 1)
void traverse_k(const float* __restrict__ values, float* __restrict__ out, int nsm) {
    extern __shared__ char sm[];
    int tid = threadIdx.x;

    unsigned smbase;
    asm("{ .reg .u64 t; cvta.to.shared.u64 t, %1; cvt.u32.u64 %0, t; }"
        : "=r"(smbase) : "l"(sm));
    unsigned mbar = smbase + SM_MBAR;

    int istart = (int)((long long)blockIdx.x * NITEMS / nsm);
    int iend   = (int)((long long)(blockIdx.x + 1) * NITEMS / nsm);

    int sl = tid & (SCHUNK - 1);
    int tl = tid >> 7;                         // warp-group 0..3
    unsigned xaddr = smbase + SM_X + sl * 4;
    int tA = 2 * tl, tB = 2 * tl + 1;
    unsigned baseA = smbase + SM_NODES + tA * (NSLOT * 8);
    unsigned baseB = smbase + SM_NODES + tB * (NSLOT * 8);
    unsigned cA = 8u - baseA, cB = 8u - baseB;

    // prologue: mbar expects 4 arrivals per phase (one per quarter)
    if (tid == 0)
        asm volatile("mbarrier.init.shared.b64 [%0], 4;" :: "r"(mbar) : "memory");
    __syncthreads();
    if (tid == 0) {
        int g0 = istart & (NGROUPS - 1);
        #pragma unroll
        for (int q = 0; q < 4; q++) fetch_quarter(smbase, g0, q, mbar);
    }
    int cur_chunk = istart >> 5;
    stage_x(sm, cur_chunk * SCHUNK, tid);
    __syncthreads();                            // x visible

    float4 vreg[4];
    float* prev_obase = out;

    for (int i = istart; i < iend; i++) {
        int k = i - istart;
        int chunk = i >> 5;
        int g = i & (NGROUPS - 1);
        int s0 = chunk * SCHUNK;
        int t0 = g * GTREES;

        if (chunk != cur_chunk) {               // all threads past prev end barrier
            stage_x(sm, s0, tid);
            cur_chunk = chunk;
            __syncthreads();                    // x visible before traversal
        }

        // issue prev item's values gather (long-latency LDGs before the wait)
        if (i > istart) {
            const unsigned* rb = (const unsigned*)(sm + SM_IDX + ((i - 1) & 1) * IDX_BYTES);
            #pragma unroll
            for (int j = 0; j < 4; j++) {
                int e = tid + THREADS * j;
                int sl2 = e >> 4, tg = (e >> 1) & 7, half = e & 1;
                unsigned vrow = rb[sl2 * IDX_PITCH + tg];
                vreg[j] = __ldg((const float4*)values + (size_t)vrow * 2 + half);
            }
        }

        mbar_wait(mbar, (unsigned)(k & 1));     // all 4 quarters of nodes[i] staged

        // ---- traversal: 2 interleaved chains, all loads from shared
        unsigned oA = baseA, oB = baseB;
        #pragma unroll
        for (int d = 0; d < DEPTH; d++) {
            unsigned ax, ay, bx, by;
            asm("ld.shared.v2.u32 {%0,%1}, [%2];" : "=r"(ax), "=r"(ay) : "r"(oA));
            asm("ld.shared.v2.u32 {%0,%1}, [%2];" : "=r"(bx), "=r"(by) : "r"(oB));
            float fa, fb;
            asm("ld.shared.f32 %0, [%1];" : "=f"(fa) : "r"(xaddr + ay));
            asm("ld.shared.f32 %0, [%1];" : "=f"(fb) : "r"(xaddr + by));
            oA = oA * 2u + cA + ((fa >= __uint_as_float(ax)) ? 8u : 0u);
            oB = oB * 2u + cB + ((fb >= __uint_as_float(bx)) ? 8u : 0u);
        }
        unsigned leafA = (oA - baseA) >> 3;     // 1023..2046
        unsigned leafB = (oB - baseB) >> 3;

        // ---- this warp-group is done reading ITS quarter: release + refill it
        //      for item i+1, overlapping the DMA with stores/idx/other groups.
        asm volatile("bar.sync %0, %1;" :: "r"(1 + tl), "r"(128) : "memory");
        if (i + 1 < iend && (tid & 127) == 0)
            fetch_quarter(smbase, (i + 1) & (NGROUPS - 1), tl, mbar);

        // ---- store prev item's gathered values (coalesced)
        if (i > istart) {
            #pragma unroll
            for (int j = 0; j < 4; j++) {
                int e = tid + THREADS * j;
                int sl2 = e >> 4, tg = (e >> 1) & 7, half = e & 1;
                *(float4*)(prev_obase + (size_t)sl2 * (NTREE * NCLS) + tg * NCLS + half * 4) = vreg[j];
            }
        }

        // ---- publish this item's values-row indices (pitch 9, conflict-free)
        {
            unsigned* wb = (unsigned*)(sm + SM_IDX + (i & 1) * IDX_BYTES);
            wb[sl * IDX_PITCH + tA] = (unsigned)(t0 + tA) * NNODE + leafA;
            wb[sl * IDX_PITCH + tB] = (unsigned)(t0 + tB) * NNODE + leafB;
        }
        __syncthreads();                        // idx visible to all groups

        prev_obase = out + (size_t)s0 * (NTREE * NCLS) + t0 * NCLS;
    }

    // epilogue: gather + store for the last item
    {
        const unsigned* rb = (const unsigned*)(sm + SM_IDX + ((iend - 1) & 1) * IDX_BYTES);
        #pragma unroll
        for (int j = 0; j < 4; j++) {
            int e = tid + THREADS * j;
            int sl2 = e >> 4, tg = (e >> 1) & 7, half = e & 1;
            unsigned vrow = rb[sl2 * IDX_PITCH + tg];
            vreg[j] = __ldg((const float4*)values + (size_t)vrow * 2 + half);
        }
        #pragma unroll
        for (int j = 0; j < 4; j++) {
            int e = tid + THREADS * j;
            int sl2 = e >> 4, tg = (e >> 1) & 7, half = e & 1;
            *(float4*)(prev_obase + (size_t)sl2 * (NTREE * NCLS) + tg * NCLS + half * 4) = vreg[j];
        }
    }
}

extern "C" void kernel_launch(void* const* d_in, const int* in_sizes, int n_in,
                              void* d_out, int out_size) {
    // metadata order: x, lefts, rights, features, thresholds, values, nodes_offset
    const float* x          = (const float*)d_in[0];
    const int*   features   = (const int*)  d_in[3];
    const float* thresholds = (const float*)d_in[4];
    const float* values     = (const float*)d_in[5];

    static int nsm = 0;                        // deterministic per-device constant
    if (nsm == 0) {
        int dev = 0;
        cudaGetDevice(&dev);
        cudaDeviceGetAttribute(&nsm, cudaDevAttrMultiProcessorCount, dev);
        if (nsm <= 0) nsm = 148;
    }

    cudaFuncSetAttribute(traverse_k, cudaFuncAttributeMaxDynamicSharedMemorySize, SM_TOTAL);

    int prep_blocks = (NFEAT / 32) * (BATCH / 32) + (NTREE * 1023 + 255) / 256;
    prep_k<<<prep_blocks, 256>>>(x, features, thresholds);
    traverse_k<<<nsm, THREADS, SM_TOTAL>>>(values, (float*)d_out, nsm);
}